// round 16
// baseline (speedup 1.0000x reference)
#include <cuda_runtime.h>
#include <cuda_bf16.h>
#include <cstdint>

#define N_NODES 50000
#define N_EDGES 800000
#define D 128

typedef unsigned int u32;

#define SCAN_T 1024
#define SCAN_C ((N_NODES + SCAN_T - 1) / SCAN_T)       // 49 per thread
#define SCAN_PAD (SCAN_T * SCAN_C)                     // 50176
#define SCAN_SMEM ((SCAN_PAD + SCAN_T) * 4)            // 204800 B = 200KB

// ---------------------------------------------------------------------------
// Scratch (device globals: allocation-free per harness rules)
// ---------------------------------------------------------------------------
__device__ float4 g_hn4[(size_t)N_NODES * D / 4];  // h_neigh (mean), 25.6MB
__device__ int    g_cnt[N_NODES];                  // in-degree
__device__ int    g_off[N_NODES];                  // CSR offsets
__device__ int    g_rank[N_EDGES];                 // edge rank within dst bucket
__device__ int    g_esrc[N_EDGES];                 // src per edge, bucketed by dst

__device__ __forceinline__ u32 f2tf32(float f) {
    u32 r; asm("cvt.rna.tf32.f32 %0, %1;" : "=r"(r) : "f"(f)); return r;
}

// ---------------------------------------------------------------------------
// K0: zero counters
// ---------------------------------------------------------------------------
__global__ void zero_kernel() {
    int i = blockIdx.x * blockDim.x + threadIdx.x;
    if (i < N_NODES) g_cnt[i] = 0;
}

// ---------------------------------------------------------------------------
// K1: degree histogram; atomic return = edge rank. 2 edges/thread for ILP.
// ---------------------------------------------------------------------------
__global__ void count_kernel(const int* __restrict__ dst_w, int st) {
    int e0 = 2 * (blockIdx.x * blockDim.x + threadIdx.x);
    if (e0 >= N_EDGES) return;
    int d0, d1;
    if (st == 1) {
        int2 dd = *(const int2*)(dst_w + e0);
        d0 = dd.x; d1 = dd.y;
    } else {
        int4 dd = *(const int4*)(dst_w + 2 * (size_t)e0);
        d0 = dd.x; d1 = dd.z;
    }
    g_rank[e0] = atomicAdd(&g_cnt[d0], 1);
    if (e0 + 1 < N_EDGES)
        g_rank[e0 + 1] = atomicAdd(&g_cnt[d1], 1);
}

// ---------------------------------------------------------------------------
// K2: single-block exclusive scan, whole 50K array staged in 200KB smem.
// Coalesced load -> per-thread chunk sums -> 1024-wide scan -> in-place
// exclusive-ize -> coalesced store. Replaces the previous 2-launch scan.
// ---------------------------------------------------------------------------
__global__ __launch_bounds__(SCAN_T)
void scan_kernel() {
    extern __shared__ int sm[];            // [SCAN_PAD] counts + [SCAN_T] partials
    int* part = sm + SCAN_PAD;
    const int t = threadIdx.x;

    // coalesced load (pad tail with 0)
    for (int i = t; i < SCAN_PAD; i += SCAN_T)
        sm[i] = (i < N_NODES) ? g_cnt[i] : 0;
    __syncthreads();

    // per-thread chunk sum
    int s = 0;
    const int base = t * SCAN_C;
#pragma unroll
    for (int j = 0; j < SCAN_C; j++) s += sm[base + j];
    part[t] = s;
    __syncthreads();

    // 1024-wide inclusive Hillis-Steele scan of partials
    for (int o = 1; o < SCAN_T; o <<= 1) {
        int x = (t >= o) ? part[t - o] : 0;
        __syncthreads();
        part[t] += x;
        __syncthreads();
    }

    // in-place exclusive-ize this thread's chunk
    int run = (t > 0) ? part[t - 1] : 0;
#pragma unroll
    for (int j = 0; j < SCAN_C; j++) {
        int v = sm[base + j];
        sm[base + j] = run;
        run += v;
    }
    __syncthreads();

    // coalesced store
    for (int i = t; i < N_NODES; i += SCAN_T)
        g_off[i] = sm[i];
}

// ---------------------------------------------------------------------------
// K3: bucket fill — NO atomics; 2 edges/thread for 2 independent chains
// ---------------------------------------------------------------------------
__global__ void fill_kernel(const int* __restrict__ src_w,
                            const int* __restrict__ dst_w, int st) {
    int e0 = 2 * (blockIdx.x * blockDim.x + threadIdx.x);
    if (e0 >= N_EDGES) return;

    int d0, d1, s0, s1;
    if (st == 1) {
        int2 dd = *(const int2*)(dst_w + e0);
        int2 ss = *(const int2*)(src_w + e0);
        d0 = dd.x; d1 = dd.y; s0 = ss.x; s1 = ss.y;
    } else {
        int4 dd = *(const int4*)(dst_w + 2 * (size_t)e0);
        int4 ss = *(const int4*)(src_w + 2 * (size_t)e0);
        d0 = dd.x; d1 = dd.z; s0 = ss.x; s1 = ss.z;
    }
    int2 rr = *(const int2*)(g_rank + e0);

    g_esrc[g_off[d0] + rr.x] = s0;
    if (e0 + 1 < N_EDGES)
        g_esrc[g_off[d1] + rr.y] = s1;
}

// ---------------------------------------------------------------------------
// K4: aggregate — one warp per node, x8-unrolled independent LDG.128 gathers
// ---------------------------------------------------------------------------
__global__ void aggregate_kernel(const float* __restrict__ feat) {
    int warp = (blockIdx.x * blockDim.x + threadIdx.x) >> 5;
    int lane = threadIdx.x & 31;
    if (warp >= N_NODES) return;

    int start = g_off[warp];
    int cnt   = g_cnt[warp];
    int end   = start + cnt;

    float4 acc = make_float4(0.f, 0.f, 0.f, 0.f);
    int e = start;
    for (; e + 8 <= end; e += 8) {
        int si[8];
#pragma unroll
        for (int k = 0; k < 8; k++) si[k] = g_esrc[e + k];   // broadcast loads
        float4 v[8];
#pragma unroll
        for (int k = 0; k < 8; k++)
            v[k] = ((const float4*)(feat + (size_t)si[k] * D))[lane];
#pragma unroll
        for (int k = 0; k < 8; k++) {
            acc.x += v[k].x; acc.y += v[k].y;
            acc.z += v[k].z; acc.w += v[k].w;
        }
    }
    for (; e < end; e++) {
        int s0 = g_esrc[e];
        float4 v0 = ((const float4*)(feat + (size_t)s0 * D))[lane];
        acc.x += v0.x; acc.y += v0.y; acc.z += v0.z; acc.w += v0.w;
    }

    float inv = 1.0f / (float)(cnt > 1 ? cnt : 1);
    acc.x *= inv; acc.y *= inv; acc.z *= inv; acc.w *= inv;
    g_hn4[(size_t)warp * (D / 4) + lane] = acc;
}

// ---------------------------------------------------------------------------
// K5: fused dual GEMM on tensor cores (tf32 mma.sync.m16n8k8):
//   out = [feat | h_neigh] @ [Ws ; Wn] + b     (virtual K = 256)
// ---------------------------------------------------------------------------
#define KC 32

__global__ __launch_bounds__(256)
void gemm_tf32_kernel(const float* __restrict__ feat,
                      const float* __restrict__ Ws,
                      const float* __restrict__ Wn,
                      const float* __restrict__ bias,
                      float* __restrict__ out) {
    __shared__ __align__(16) u32 A_s[128][36];
    __shared__ __align__(16) u32 B_s[KC][132];

    const int tid  = threadIdx.x;
    const int wid  = tid >> 5;
    const int lane = tid & 31;
    const int wm   = wid >> 2;
    const int wn   = wid & 3;
    const int gid  = lane >> 2;
    const int t4   = lane & 3;
    const int node0 = blockIdx.x * 128;
    const float* hng = (const float*)g_hn4;

    float d[4][4][4];
#pragma unroll
    for (int mt = 0; mt < 4; mt++)
#pragma unroll
        for (int nt = 0; nt < 4; nt++)
#pragma unroll
            for (int r = 0; r < 4; r++) d[mt][nt][r] = 0.f;

    for (int kc = 0; kc < 2 * D; kc += KC) {
        const float* Asrc = (kc < D) ? (feat + kc) : (hng + (kc - D));
        {
            int r  = tid >> 3;
            int c4 = (tid & 7) * 4;
#pragma unroll
            for (int rr = 0; rr < 128; rr += 32) {
                int gn = node0 + r + rr;
                float4 v = make_float4(0.f, 0.f, 0.f, 0.f);
                if (gn < N_NODES) v = *(const float4*)(Asrc + (size_t)gn * D + c4);
                uint4 u;
                u.x = f2tf32(v.x); u.y = f2tf32(v.y);
                u.z = f2tf32(v.z); u.w = f2tf32(v.w);
                *(uint4*)&A_s[r + rr][c4] = u;
            }
        }
        const float* Bsrc = (kc < D) ? (Ws + (size_t)kc * D)
                                     : (Wn + (size_t)(kc - D) * D);
#pragma unroll
        for (int j = 0; j < 4; j++) {
            int idx = tid + j * 256;
            int row = idx >> 5;
            int c4  = (idx & 31) * 4;
            float4 v = *(const float4*)(Bsrc + (size_t)row * D + c4);
            uint4 u;
            u.x = f2tf32(v.x); u.y = f2tf32(v.y);
            u.z = f2tf32(v.z); u.w = f2tf32(v.w);
            *(uint4*)&B_s[row][c4] = u;
        }
        __syncthreads();

#pragma unroll
        for (int kk = 0; kk < KC; kk += 8) {
            u32 bf[4][2];
#pragma unroll
            for (int nt = 0; nt < 4; nt++) {
                int col = wn * 32 + nt * 8 + gid;
                bf[nt][0] = B_s[kk + t4][col];
                bf[nt][1] = B_s[kk + t4 + 4][col];
            }
#pragma unroll
            for (int mt = 0; mt < 4; mt++) {
                int row = wm * 64 + mt * 16 + gid;
                u32 a0 = A_s[row][kk + t4];
                u32 a1 = A_s[row + 8][kk + t4];
                u32 a2 = A_s[row][kk + t4 + 4];
                u32 a3 = A_s[row + 8][kk + t4 + 4];
#pragma unroll
                for (int nt = 0; nt < 4; nt++) {
                    asm volatile(
                        "mma.sync.aligned.m16n8k8.row.col.f32.tf32.tf32.f32 "
                        "{%0,%1,%2,%3}, {%4,%5,%6,%7}, {%8,%9}, {%0,%1,%2,%3};"
                        : "+f"(d[mt][nt][0]), "+f"(d[mt][nt][1]),
                          "+f"(d[mt][nt][2]), "+f"(d[mt][nt][3])
                        : "r"(a0), "r"(a1), "r"(a2), "r"(a3),
                          "r"(bf[nt][0]), "r"(bf[nt][1]));
                }
            }
        }
        __syncthreads();
    }

#pragma unroll
    for (int nt = 0; nt < 4; nt++) {
        int col = wn * 32 + nt * 8 + 2 * t4;
        float2 bb = *(const float2*)(bias + col);
#pragma unroll
        for (int mt = 0; mt < 4; mt++) {
            int row = node0 + wm * 64 + mt * 16 + gid;
            if (row < N_NODES) {
                float2 o0; o0.x = d[mt][nt][0] + bb.x; o0.y = d[mt][nt][1] + bb.y;
                *(float2*)(out + (size_t)row * D + col) = o0;
            }
            if (row + 8 < N_NODES) {
                float2 o1; o1.x = d[mt][nt][2] + bb.x; o1.y = d[mt][nt][3] + bb.y;
                *(float2*)(out + (size_t)(row + 8) * D + col) = o1;
            }
        }
    }
}

// ---------------------------------------------------------------------------
// Launch: 6 kernels
// ---------------------------------------------------------------------------
extern "C" void kernel_launch(void* const* d_in, const int* in_sizes, int n_in,
                              void* d_out, int out_size) {
    const float* feat  = (const float*)d_in[0];
    const int*   src_w = (const int*)d_in[1];
    const int*   dst_w = (const int*)d_in[2];
    const float* Ws    = (const float*)d_in[3];
    const float* Wn    = (const float*)d_in[4];
    const float* b     = (const float*)d_in[5];
    float*       out   = (float*)d_out;

    const int st = (in_sizes[2] >= 2 * N_EDGES) ? 2 : 1;   // int64 -> 2 words

    // opt-in to 200KB dynamic smem for the single-block scan (host-side
    // attribute set; not a stream op, graph-capture safe, idempotent)
    cudaFuncSetAttribute(scan_kernel,
                         cudaFuncAttributeMaxDynamicSharedMemorySize, SCAN_SMEM);

    zero_kernel<<<(N_NODES + 255) / 256, 256>>>();
    count_kernel<<<(N_EDGES / 2 + 255) / 256, 256>>>(dst_w, st);
    scan_kernel<<<1, SCAN_T, SCAN_SMEM>>>();
    fill_kernel<<<(N_EDGES / 2 + 255) / 256, 256>>>(src_w, dst_w, st);

    {   // aggregate: one warp per node
        int threads = 256;
        int blocks = (N_NODES * 32 + threads - 1) / threads;
        aggregate_kernel<<<blocks, threads>>>(feat);
    }

    {   // fused dual GEMM on tensor cores
        int blocks = (N_NODES + 127) / 128;
        gemm_tf32_kernel<<<blocks, 256>>>(feat, Ws, Wn, b, out);
    }
}

// round 17
// speedup vs baseline: 1.0842x; 1.0842x over previous
#include <cuda_runtime.h>
#include <cuda_bf16.h>
#include <cstdint>

#define N_NODES 50000
#define N_EDGES 800000
#define D 128

typedef unsigned int u32;

#define SCAN_CHUNK 1024
#define SCAN_BLOCKS ((N_NODES + SCAN_CHUNK - 1) / SCAN_CHUNK)  // 49

// ---------------------------------------------------------------------------
// Scratch (device globals: allocation-free per harness rules)
// ---------------------------------------------------------------------------
__device__ float4 g_hn4[(size_t)N_NODES * D / 4];  // h_neigh (mean), 25.6MB
__device__ int    g_cnt[N_NODES];                  // in-degree
__device__ int    g_off[N_NODES];                  // CSR offsets
__device__ int    g_rank[N_EDGES];                 // edge rank within dst bucket
__device__ int    g_esrc[N_EDGES];                 // src per edge, bucketed by dst
__device__ int    g_bsum[SCAN_BLOCKS];             // scan block sums

__device__ __forceinline__ u32 f2tf32(float f) {
    u32 r; asm("cvt.rna.tf32.f32 %0, %1;" : "=r"(r) : "f"(f)); return r;
}

// ---------------------------------------------------------------------------
// K0: zero counters
// ---------------------------------------------------------------------------
__global__ void zero_kernel() {
    int i = blockIdx.x * blockDim.x + threadIdx.x;
    if (i < N_NODES) g_cnt[i] = 0;
}

// ---------------------------------------------------------------------------
// K1: degree histogram; atomic return = edge rank. 2 edges/thread for ILP.
// ---------------------------------------------------------------------------
__global__ void count_kernel(const int* __restrict__ dst_w, int st) {
    int e0 = 2 * (blockIdx.x * blockDim.x + threadIdx.x);
    if (e0 >= N_EDGES) return;
    int d0, d1;
    if (st == 1) {
        int2 dd = *(const int2*)(dst_w + e0);
        d0 = dd.x; d1 = dd.y;
    } else {
        int4 dd = *(const int4*)(dst_w + 2 * (size_t)e0);
        d0 = dd.x; d1 = dd.z;
    }
    g_rank[e0] = atomicAdd(&g_cnt[d0], 1);
    if (e0 + 1 < N_EDGES)
        g_rank[e0 + 1] = atomicAdd(&g_cnt[d1], 1);
}

// ---------------------------------------------------------------------------
// K2a: per-block totals (measured-best 2-launch scan; the 1-block 200KB-smem
// variant serialized on one SM and cost +7.7us)
// ---------------------------------------------------------------------------
__global__ void scan1_kernel() {
    __shared__ int ssum[256];
    int b = blockIdx.x, t = threadIdx.x;
    int base = b * SCAN_CHUNK;
    int s = 0;
#pragma unroll
    for (int i = t; i < SCAN_CHUNK; i += 256) {
        int idx = base + i;
        if (idx < N_NODES) s += g_cnt[idx];
    }
    ssum[t] = s;
    __syncthreads();
    for (int o = 128; o > 0; o >>= 1) {
        if (t < o) ssum[t] += ssum[t + o];
        __syncthreads();
    }
    if (t == 0) g_bsum[b] = ssum[0];
}

// ---------------------------------------------------------------------------
// K2b: per-block exclusive scan + base; each block redundantly scans the 49
// block totals in smem (no separate scan2 launch)
// ---------------------------------------------------------------------------
__global__ void scan3_kernel() {
    __shared__ int tsum[256];
    __shared__ int bsc[64];
    int b = blockIdx.x, t = threadIdx.x;

    if (t < 64) bsc[t] = (t < SCAN_BLOCKS) ? g_bsum[t] : 0;
    __syncthreads();
    for (int o = 1; o < 64; o <<= 1) {
        int x = 0;
        if (t < 64 && t >= o) x = bsc[t - o];
        __syncthreads();
        if (t < 64) bsc[t] += x;
        __syncthreads();
    }
    const int block_base = (b > 0) ? bsc[b - 1] : 0;

    int idx0 = b * SCAN_CHUNK + t * 4;
    int v[4], s = 0;
#pragma unroll
    for (int j = 0; j < 4; j++) {
        int idx = idx0 + j;
        v[j] = (idx < N_NODES) ? g_cnt[idx] : 0;
        s += v[j];
    }
    tsum[t] = s;
    __syncthreads();
    for (int o = 1; o < 256; o <<= 1) {
        int x = (t >= o) ? tsum[t - o] : 0;
        __syncthreads();
        tsum[t] += x;
        __syncthreads();
    }
    int run = block_base + (t > 0 ? tsum[t - 1] : 0);
#pragma unroll
    for (int j = 0; j < 4; j++) {
        int idx = idx0 + j;
        if (idx < N_NODES) g_off[idx] = run;
        run += v[j];
    }
}

// ---------------------------------------------------------------------------
// K3: bucket fill — NO atomics; 4 edges/thread (4 independent latency chains;
// fill is latency-bound: issue was 5.2% at occ 70%)
// ---------------------------------------------------------------------------
__global__ void fill_kernel(const int* __restrict__ src_w,
                            const int* __restrict__ dst_w, int st) {
    int e0 = 4 * (blockIdx.x * blockDim.x + threadIdx.x);
    if (e0 >= N_EDGES) return;

    int d[4], s[4];
    if (st == 1) {
        int4 dd = *(const int4*)(dst_w + e0);
        int4 ss = *(const int4*)(src_w + e0);
        d[0] = dd.x; d[1] = dd.y; d[2] = dd.z; d[3] = dd.w;
        s[0] = ss.x; s[1] = ss.y; s[2] = ss.z; s[3] = ss.w;
    } else {
        int4 dd0 = *(const int4*)(dst_w + 2 * (size_t)e0);
        int4 dd1 = *(const int4*)(dst_w + 2 * (size_t)e0 + 4);
        int4 ss0 = *(const int4*)(src_w + 2 * (size_t)e0);
        int4 ss1 = *(const int4*)(src_w + 2 * (size_t)e0 + 4);
        d[0] = dd0.x; d[1] = dd0.z; d[2] = dd1.x; d[3] = dd1.z;
        s[0] = ss0.x; s[1] = ss0.z; s[2] = ss1.x; s[3] = ss1.z;
    }
    int4 rr = *(const int4*)(g_rank + e0);
    int r[4] = {rr.x, rr.y, rr.z, rr.w};

    int o[4];
#pragma unroll
    for (int k = 0; k < 4; k++)
        if (e0 + k < N_EDGES) o[k] = g_off[d[k]];
#pragma unroll
    for (int k = 0; k < 4; k++)
        if (e0 + k < N_EDGES) g_esrc[o[k] + r[k]] = s[k];
}

// ---------------------------------------------------------------------------
// K4: aggregate — one warp per node, x8-unrolled independent LDG.128 gathers
// ---------------------------------------------------------------------------
__global__ void aggregate_kernel(const float* __restrict__ feat) {
    int warp = (blockIdx.x * blockDim.x + threadIdx.x) >> 5;
    int lane = threadIdx.x & 31;
    if (warp >= N_NODES) return;

    int start = g_off[warp];
    int cnt   = g_cnt[warp];
    int end   = start + cnt;

    float4 acc = make_float4(0.f, 0.f, 0.f, 0.f);
    int e = start;
    for (; e + 8 <= end; e += 8) {
        int si[8];
#pragma unroll
        for (int k = 0; k < 8; k++) si[k] = g_esrc[e + k];   // broadcast loads
        float4 v[8];
#pragma unroll
        for (int k = 0; k < 8; k++)
            v[k] = ((const float4*)(feat + (size_t)si[k] * D))[lane];
#pragma unroll
        for (int k = 0; k < 8; k++) {
            acc.x += v[k].x; acc.y += v[k].y;
            acc.z += v[k].z; acc.w += v[k].w;
        }
    }
    for (; e < end; e++) {
        int s0 = g_esrc[e];
        float4 v0 = ((const float4*)(feat + (size_t)s0 * D))[lane];
        acc.x += v0.x; acc.y += v0.y; acc.z += v0.z; acc.w += v0.w;
    }

    float inv = 1.0f / (float)(cnt > 1 ? cnt : 1);
    acc.x *= inv; acc.y *= inv; acc.z *= inv; acc.w *= inv;
    g_hn4[(size_t)warp * (D / 4) + lane] = acc;
}

// ---------------------------------------------------------------------------
// K5: fused dual GEMM on tensor cores (tf32 mma.sync.m16n8k8):
//   out = [feat | h_neigh] @ [Ws ; Wn] + b     (virtual K = 256)
// ---------------------------------------------------------------------------
#define KC 32

__global__ __launch_bounds__(256)
void gemm_tf32_kernel(const float* __restrict__ feat,
                      const float* __restrict__ Ws,
                      const float* __restrict__ Wn,
                      const float* __restrict__ bias,
                      float* __restrict__ out) {
    __shared__ __align__(16) u32 A_s[128][36];
    __shared__ __align__(16) u32 B_s[KC][132];

    const int tid  = threadIdx.x;
    const int wid  = tid >> 5;
    const int lane = tid & 31;
    const int wm   = wid >> 2;
    const int wn   = wid & 3;
    const int gid  = lane >> 2;
    const int t4   = lane & 3;
    const int node0 = blockIdx.x * 128;
    const float* hng = (const float*)g_hn4;

    float d[4][4][4];
#pragma unroll
    for (int mt = 0; mt < 4; mt++)
#pragma unroll
        for (int nt = 0; nt < 4; nt++)
#pragma unroll
            for (int r = 0; r < 4; r++) d[mt][nt][r] = 0.f;

    for (int kc = 0; kc < 2 * D; kc += KC) {
        const float* Asrc = (kc < D) ? (feat + kc) : (hng + (kc - D));
        {
            int r  = tid >> 3;
            int c4 = (tid & 7) * 4;
#pragma unroll
            for (int rr = 0; rr < 128; rr += 32) {
                int gn = node0 + r + rr;
                float4 v = make_float4(0.f, 0.f, 0.f, 0.f);
                if (gn < N_NODES) v = *(const float4*)(Asrc + (size_t)gn * D + c4);
                uint4 u;
                u.x = f2tf32(v.x); u.y = f2tf32(v.y);
                u.z = f2tf32(v.z); u.w = f2tf32(v.w);
                *(uint4*)&A_s[r + rr][c4] = u;
            }
        }
        const float* Bsrc = (kc < D) ? (Ws + (size_t)kc * D)
                                     : (Wn + (size_t)(kc - D) * D);
#pragma unroll
        for (int j = 0; j < 4; j++) {
            int idx = tid + j * 256;
            int row = idx >> 5;
            int c4  = (idx & 31) * 4;
            float4 v = *(const float4*)(Bsrc + (size_t)row * D + c4);
            uint4 u;
            u.x = f2tf32(v.x); u.y = f2tf32(v.y);
            u.z = f2tf32(v.z); u.w = f2tf32(v.w);
            *(uint4*)&B_s[row][c4] = u;
        }
        __syncthreads();

#pragma unroll
        for (int kk = 0; kk < KC; kk += 8) {
            u32 bf[4][2];
#pragma unroll
            for (int nt = 0; nt < 4; nt++) {
                int col = wn * 32 + nt * 8 + gid;
                bf[nt][0] = B_s[kk + t4][col];
                bf[nt][1] = B_s[kk + t4 + 4][col];
            }
#pragma unroll
            for (int mt = 0; mt < 4; mt++) {
                int row = wm * 64 + mt * 16 + gid;
                u32 a0 = A_s[row][kk + t4];
                u32 a1 = A_s[row + 8][kk + t4];
                u32 a2 = A_s[row][kk + t4 + 4];
                u32 a3 = A_s[row + 8][kk + t4 + 4];
#pragma unroll
                for (int nt = 0; nt < 4; nt++) {
                    asm volatile(
                        "mma.sync.aligned.m16n8k8.row.col.f32.tf32.tf32.f32 "
                        "{%0,%1,%2,%3}, {%4,%5,%6,%7}, {%8,%9}, {%0,%1,%2,%3};"
                        : "+f"(d[mt][nt][0]), "+f"(d[mt][nt][1]),
                          "+f"(d[mt][nt][2]), "+f"(d[mt][nt][3])
                        : "r"(a0), "r"(a1), "r"(a2), "r"(a3),
                          "r"(bf[nt][0]), "r"(bf[nt][1]));
                }
            }
        }
        __syncthreads();
    }

#pragma unroll
    for (int nt = 0; nt < 4; nt++) {
        int col = wn * 32 + nt * 8 + 2 * t4;
        float2 bb = *(const float2*)(bias + col);
#pragma unroll
        for (int mt = 0; mt < 4; mt++) {
            int row = node0 + wm * 64 + mt * 16 + gid;
            if (row < N_NODES) {
                float2 o0; o0.x = d[mt][nt][0] + bb.x; o0.y = d[mt][nt][1] + bb.y;
                *(float2*)(out + (size_t)row * D + col) = o0;
            }
            if (row + 8 < N_NODES) {
                float2 o1; o1.x = d[mt][nt][2] + bb.x; o1.y = d[mt][nt][3] + bb.y;
                *(float2*)(out + (size_t)(row + 8) * D + col) = o1;
            }
        }
    }
}

// ---------------------------------------------------------------------------
// Launch: 7 kernels
// ---------------------------------------------------------------------------
extern "C" void kernel_launch(void* const* d_in, const int* in_sizes, int n_in,
                              void* d_out, int out_size) {
    const float* feat  = (const float*)d_in[0];
    const int*   src_w = (const int*)d_in[1];
    const int*   dst_w = (const int*)d_in[2];
    const float* Ws    = (const float*)d_in[3];
    const float* Wn    = (const float*)d_in[4];
    const float* b     = (const float*)d_in[5];
    float*       out   = (float*)d_out;

    const int st = (in_sizes[2] >= 2 * N_EDGES) ? 2 : 1;   // int64 -> 2 words

    zero_kernel<<<(N_NODES + 255) / 256, 256>>>();
    count_kernel<<<(N_EDGES / 2 + 255) / 256, 256>>>(dst_w, st);
    scan1_kernel<<<SCAN_BLOCKS, 256>>>();
    scan3_kernel<<<SCAN_BLOCKS, 256>>>();
    fill_kernel<<<(N_EDGES / 4 + 255) / 256, 256>>>(src_w, dst_w, st);

    {   // aggregate: one warp per node
        int threads = 256;
        int blocks = (N_NODES * 32 + threads - 1) / threads;
        aggregate_kernel<<<blocks, threads>>>(feat);
    }

    {   // fused dual GEMM on tensor cores
        int blocks = (N_NODES + 127) / 128;
        gemm_tf32_kernel<<<blocks, 256>>>(feat, Ws, Wn, b, out);
    }
}